// round 12
// baseline (speedup 1.0000x reference)
#include <cuda_runtime.h>
#include <cstdint>

#define NUM_A   98304
#define NUM_T   1024
#define NCLS    21
#define NLOGIT  (NUM_A * NCLS)
#define NVEC    (NLOGIT / 4)            // 516096

#define GB      32
#define CELLS   (GB * GB)

#define BLK     128
#define APT     2
#define WSPLIT  6
#define AGRP    (NUM_A / (BLK * APT))   // 384 anchor groups (256 anchors each)
#define MATCHB  (AGRP * WSPLIT)         // 2304 blocks
#define FSLICE  (NVEC / MATCHB)         // 224 float4 per block (exact)

#define PREPB   256
#define PREPG   (NUM_A / PREPB)         // 384

typedef unsigned long long ull;

// ---------------- device scratch (zero-init; self-restoring) -----------------
__device__ float4   g_tbox_s[NUM_T];
__device__ int      g_tid_s[NUM_T];
__device__ int      g_toff[CELLS + 1];

__device__ int      g_acnt[CELLS];      // reset by final block
__device__ int      g_aoff[CELLS + 1];
__device__ int      g_acell[NUM_A];
__device__ int      g_arank[NUM_A];
__device__ float4   g_abox_s[NUM_A];
__device__ int      g_aid_s[NUM_A];

__device__ ull      g_akey[NUM_A];      // atomicMax; zeroed in ascatter
__device__ ull      g_tkey[NUM_T];      // atomicMax (sorted idx); reset by final
__device__ int      g_gdone[AGRP];      // per-group tickets; reset after use
__device__ double   g_cls_sum;          // reset by final block
__device__ int      g_npos;             // reset by final block
__device__ unsigned g_ticket;           // reset by final block

// fast negative-class focal: 0.75 * sigmoid(x)^2 * softplus(x); 3 MUFU ops
__device__ __forceinline__ float focal_neg(float x) {
    float u = exp2f(x * 1.4426950408889634f);
    float d = u + 1.0f;
    float q; asm("rcp.approx.f32 %0, %1;" : "=f"(q) : "f"(d));
    float lg = __log2f(d);
    float p  = u * q;
    return (0.75f * 0.6931471805599453f) * (p * p) * lg;
}

__device__ __forceinline__ int cell_of(float cx, float cy) {
    int bx = min(GB - 1, max(0, (int)(cx * (float)GB)));
    int by = min(GB - 1, max(0, (int)(cy * (float)GB)));
    return by * GB + bx;
}

__device__ __forceinline__ float sl1(float d) {
    float ad = fabsf(d);
    return (ad < 1.0f) ? 0.5f * d * d : ad - 0.5f;
}

// fast 1024-thread inclusive scan (3-phase shfl)
__device__ __forceinline__ int scan1024(int v, int tid, int* wsum) {
    int lane = tid & 31, wid = tid >> 5;
    #pragma unroll
    for (int o = 1; o < 32; o <<= 1) {
        int n = __shfl_up_sync(0xFFFFFFFFu, v, o);
        if (lane >= o) v += n;
    }
    if (lane == 31) wsum[wid] = v;
    __syncthreads();
    if (wid == 0) {
        int s = wsum[lane];
        #pragma unroll
        for (int o = 1; o < 32; o <<= 1) {
            int n = __shfl_up_sync(0xFFFFFFFFu, s, o);
            if (lane >= o) s += n;
        }
        wsum[lane] = s;
    }
    __syncthreads();
    return v + (wid > 0 ? wsum[wid - 1] : 0);
}

// ---------------- L1: anchor cell + rank -------------------------------------
__global__ void __launch_bounds__(PREPB) acount_kernel(
    const float* __restrict__ anchors)
{
    const int a = blockIdx.x * PREPB + threadIdx.x;
    float4 ab = ((const float4*)anchors)[a];
    int cell = cell_of(0.5f * (ab.x + ab.z), 0.5f * (ab.y + ab.w));
    g_acell[a] = cell;
    g_arank[a] = atomicAdd(&g_acnt[cell], 1);
}

// ---------------- L2: target CSR + anchor offset scan (1 block) --------------
__global__ void __launch_bounds__(NUM_T) prep_kernel(
    const float* __restrict__ tboxes)
{
    __shared__ int tcnt[CELLS];
    __shared__ int texcl[CELLS];
    __shared__ int wsum[32];
    const int tid = threadIdx.x;

    tcnt[tid] = 0;
    __syncthreads();

    float4 b = ((const float4*)tboxes)[tid];
    int cell = cell_of(0.5f * (b.x + b.z), 0.5f * (b.y + b.w));
    int rank = atomicAdd(&tcnt[cell], 1);
    __syncthreads();

    int incl = scan1024(tcnt[tid], tid, wsum);
    int excl = incl - tcnt[tid];
    g_toff[tid] = excl;
    texcl[tid] = excl;
    if (tid == 0) g_toff[CELLS] = NUM_T;
    __syncthreads();

    int pos = texcl[cell] + rank;
    g_tbox_s[pos] = b;
    g_tid_s[pos]  = tid;

    __syncthreads();
    int ai = scan1024(g_acnt[tid], tid, wsum);
    g_aoff[tid] = ai - g_acnt[tid];
    if (tid == 0) g_aoff[CELLS] = NUM_A;
}

// ---------------- L3: anchor scatter + g_akey zero ---------------------------
__global__ void __launch_bounds__(PREPB) ascatter_kernel(
    const float* __restrict__ anchors)
{
    const int a = blockIdx.x * PREPB + threadIdx.x;
    int pos = g_aoff[g_acell[a]] + g_arank[a];
    g_abox_s[pos] = ((const float4*)anchors)[a];
    g_aid_s[pos]  = a;
    g_akey[a]     = 0ULL;
}

// ---------------- L4: fused match + focal + inlined epilogue -----------------
__global__ void __launch_bounds__(BLK, 10) fused_kernel(
    const float* __restrict__ cls_preds,
    const int*   __restrict__ tlabels,
    const float* __restrict__ boxes_preds,
    const float* __restrict__ anchors,
    const float* __restrict__ tboxes,
    float* __restrict__ out)
{
    const int tid  = threadIdx.x;
    const int grp  = blockIdx.x / WSPLIT;
    const int part = blockIdx.x % WSPLIT;

    const int sp0 = grp * (BLK * APT) + 2 * tid;   // adjacent sorted anchors
    const float4 ab0 = g_abox_s[sp0];
    const float4 ab1 = g_abox_s[sp0 + 1];
    const int orig0 = g_aid_s[sp0];
    const int orig1 = g_aid_s[sp0 + 1];

    const float aw0 = ab0.z - ab0.x, ah0 = ab0.w - ab0.y;
    const float aw1 = ab1.z - ab1.x, ah1 = ab1.w - ab1.y;
    const float area0 = aw0 * ah0;
    const float area1 = aw1 * ah1;

    const float acx0 = 0.5f * (ab0.x + ab0.z), acy0 = 0.5f * (ab0.y + ab0.w);
    const float acx1 = 0.5f * (ab1.x + ab1.z), acy1 = 0.5f * (ab1.y + ab1.w);
    const float Rx0 = 0.55f * fminf(aw0 * 2.2223f, 0.34f);
    const float Ry0 = 0.55f * fminf(ah0 * 2.2223f, 0.34f);
    const float Rx1 = 0.55f * fminf(aw1 * 2.2223f, 0.34f);
    const float Ry1 = 0.55f * fminf(ah1 * 2.2223f, 0.34f);
    float xlo = fminf(acx0 - Rx0, acx1 - Rx1);
    float xhi = fmaxf(acx0 + Rx0, acx1 + Rx1);
    float ylo = fminf(acy0 - Ry0, acy1 - Ry1);
    float yhi = fmaxf(acy0 + Ry0, acy1 + Ry1);
    int clo = max(0, (int)(xlo * (float)GB));
    int chi = min(GB - 1, (int)(xhi * (float)GB));
    int rlo = max(0, (int)(ylo * (float)GB));
    int rhi = min(GB - 1, (int)(yhi * (float)GB));

    int clo_w = __reduce_min_sync(0xFFFFFFFFu, (unsigned)clo);
    int chi_w = __reduce_max_sync(0xFFFFFFFFu, (unsigned)chi);
    int rlo_w = __reduce_min_sync(0xFFFFFFFFu, (unsigned)rlo);
    int rhi_w = __reduce_max_sync(0xFFFFFFFFu, (unsigned)rhi);

    int len = rhi_w - rlo_w + 1;
    int r0 = rlo_w + (len * part)       / WSPLIT;
    int r1 = rlo_w + (len * (part + 1)) / WSPLIT - 1;

    float bi0 = 0.0f, bS0 = 1.0f, bi1 = 0.0f, bS1 = 1.0f;
    int   bt0 = 0, bt1 = 0;

    for (int r = r0; r <= r1; ++r) {
        int j  = g_toff[(r << 5) + clo_w];
        int je = g_toff[(r << 5) + chi_w + 1];
        #pragma unroll 2
        for (; j < je; ++j) {
            float4 tb = __ldg(&g_tbox_s[j]);
            float ta = (tb.z - tb.x) * (tb.w - tb.y);

            float lx0 = fmaxf(ab0.x, tb.x), ly0 = fmaxf(ab0.y, tb.y);
            float rx0 = fminf(ab0.z, tb.z), ry0 = fminf(ab0.w, tb.w);
            float w0  = fmaxf(rx0 - lx0, 0.0f);
            float in0 = w0 * (ry0 - ly0);
            float S0  = area0 + ta;
            bool p0 = in0 * bS0 > bi0 * S0;
            if (p0) { bi0 = in0; bS0 = S0; bt0 = j; }
            bool c0 = in0 > 0.3103448f * S0;       // iou > 0.45

            float lx1 = fmaxf(ab1.x, tb.x), ly1 = fmaxf(ab1.y, tb.y);
            float rx1 = fminf(ab1.z, tb.z), ry1 = fminf(ab1.w, tb.w);
            float w1  = fmaxf(rx1 - lx1, 0.0f);
            float in1 = w1 * (ry1 - ly1);
            float S1  = area1 + ta;
            bool p1 = in1 * bS1 > bi1 * S1;
            if (p1) { bi1 = in1; bS1 = S1; bt1 = j; }
            bool c1 = in1 > 0.3103448f * S1;

            if (__ballot_sync(0xFFFFFFFFu, c0 || c1)) {
                ull k = 0ULL;
                if (c0) {
                    float iou = __fdividef(in0, S0 - in0);
                    k = ((ull)__float_as_uint(iou) << 32)
                      | (ull)(0xFFFFFFFFu - (unsigned)orig0);
                }
                if (c1) {
                    float iou = __fdividef(in1, S1 - in1);
                    ull k1 = ((ull)__float_as_uint(iou) << 32)
                           | (ull)(0xFFFFFFFFu - (unsigned)orig1);
                    k = (k1 > k) ? k1 : k;
                }
                #pragma unroll
                for (int o = 16; o > 0; o >>= 1) {
                    ull other = __shfl_xor_sync(0xFFFFFFFFu, k, o);
                    k = (other > k) ? other : k;
                }
                if ((tid & 31) == 0) atomicMax(&g_tkey[j], k);
            }
        }
    }

    {
        float iou0 = __fdividef(bi0, bS0 - bi0);
        atomicMax(&g_akey[orig0],
                  ((ull)__float_as_uint(iou0) << 32)
                  | (ull)(0xFFFFFFFFu - (unsigned)bt0));
        float iou1 = __fdividef(bi1, bS1 - bi1);
        atomicMax(&g_akey[orig1],
                  ((ull)__float_as_uint(iou1) << 32)
                  | (ull)(0xFFFFFFFFu - (unsigned)bt1));
    }

    // ---- uniform focal slice ------------------------------------------------
    {
        const float4* cp = (const float4*)cls_preds;
        const int lo = blockIdx.x * FSLICE;
        float acc = 0.0f;
        for (int i = lo + tid; i < lo + FSLICE; i += BLK) {
            float4 v = cp[i];
            acc += focal_neg(v.x) + focal_neg(v.y)
                 + focal_neg(v.z) + focal_neg(v.w);
        }
        #pragma unroll
        for (int o = 16; o > 0; o >>= 1)
            acc += __shfl_down_sync(0xFFFFFFFFu, acc, o);
        __shared__ float rs[4];
        if ((tid & 31) == 0) rs[tid >> 5] = acc;
        __syncthreads();
        if (tid == 0)
            atomicAdd(&g_cls_sum, (double)(rs[0] + rs[1] + rs[2] + rs[3]));
    }

    // ---- group epilogue: last of the 6 sibling blocks -----------------------
    __shared__ int lastg;
    __threadfence();
    if (tid == 0) lastg = (atomicAdd(&g_gdone[grp], 1) == WSPLIT - 1);
    __syncthreads();
    if (lastg) {
        float delta = 0.0f;
        int   np = 0;
        #pragma unroll
        for (int k = 0; k < APT; ++k) {
            int sp = grp * (BLK * APT) + k * BLK + tid;
            int a  = g_aid_s[sp];
            ull key = __ldcg(&g_akey[a]);
            float iou = __uint_as_float((unsigned)(key >> 32));
            if (iou >= 0.5f) {
                np++;
                int ts = (int)(0xFFFFFFFFu - (unsigned)(key & 0xFFFFFFFFull));
                int L = tlabels[g_tid_s[ts]];
                float x = cls_preds[(size_t)a * NCLS + L];
                float ax = fabsf(x);
                float ce = fmaxf(x, 0.0f) - x + log1pf(expf(-ax));
                float pp = 1.0f / (1.0f + expf(-x));
                float om = 1.0f - pp;
                delta += 0.25f * om * om * ce - focal_neg(x);
            }
        }
        #pragma unroll
        for (int o = 16; o > 0; o >>= 1) {
            delta += __shfl_down_sync(0xFFFFFFFFu, delta, o);
            np    += __shfl_down_sync(0xFFFFFFFFu, np,    o);
        }
        __shared__ float ds[4];
        __shared__ int   ns[4];
        if ((tid & 31) == 0) { ds[tid >> 5] = delta; ns[tid >> 5] = np; }
        __syncthreads();
        if (tid == 0) {
            atomicAdd(&g_cls_sum, (double)(ds[0] + ds[1] + ds[2] + ds[3]));
            atomicAdd(&g_npos, ns[0] + ns[1] + ns[2] + ns[3]);
            g_gdone[grp] = 0;                      // restore for next replay
        }
    }

    // ---- global final: last block overall -----------------------------------
    __shared__ int lastb;
    __threadfence();
    if (tid == 0) lastb = (atomicAdd(&g_ticket, 1u) == MATCHB - 1);
    __syncthreads();
    if (!lastb) return;

    for (int i = tid; i < CELLS; i += BLK) g_acnt[i] = 0;  // restore

    float loss = 0.0f;
    int   nm = 0;
    for (int t = tid; t < NUM_T; t += BLK) {
        ull k = __ldcg(&g_tkey[t]);
        g_tkey[t] = 0ULL;                          // restore for next replay
        float tiou = __uint_as_float((unsigned)(k >> 32));
        if (tiou >= 0.5f) {
            nm++;
            int tor = g_tid_s[t];
            unsigned aidx = 0xFFFFFFFFu - (unsigned)(k & 0xFFFFFFFFull);
            float4 abx = ((const float4*)anchors)[aidx];
            float4 tb  = ((const float4*)tboxes)[tor];
            float4 pr  = ((const float4*)boxes_preds)[aidx];
            float bw = tb.z - tb.x, bh = tb.w - tb.y;
            float bcx = tb.x + 0.5f * bw, bcy = tb.y + 0.5f * bh;
            float aww = abx.z - abx.x, ahh = abx.w - abx.y;
            float acx = abx.x + 0.5f * aww, acy = abx.y + 0.5f * ahh;
            float tx = (bcx - acx) / aww;
            float ty = (bcy - acy) / ahh;
            float tw = logf(fmaxf(bw, 1e-8f) / aww);
            float th = logf(fmaxf(bh, 1e-8f) / ahh);
            loss += sl1(pr.x - tx) + sl1(pr.y - ty)
                  + sl1(pr.z - tw) + sl1(pr.w - th);
        }
    }
    #pragma unroll
    for (int o = 16; o > 0; o >>= 1) {
        loss += __shfl_down_sync(0xFFFFFFFFu, loss, o);
        nm   += __shfl_down_sync(0xFFFFFFFFu, nm,   o);
    }
    __shared__ float frs[4];
    __shared__ int   frm[4];
    if ((tid & 31) == 0) { frs[tid >> 5] = loss; frm[tid >> 5] = nm; }
    __syncthreads();
    if (tid == 0) {
        float total = frs[0] + frs[1] + frs[2] + frs[3];
        int   tm    = frm[0] + frm[1] + frm[2] + frm[3];
        double cls_total = atomicAdd(&g_cls_sum, 0.0);
        int    npos      = atomicAdd(&g_npos, 0);
        double n_match   = (tm > 0) ? (double)tm : 1.0;
        double cls = cls_total / (double)npos;
        double reg = (double)total / (n_match * 4.0);
        out[0] = (float)(cls + reg);
        out[1] = (float)cls;
        out[2] = (float)reg;
        g_cls_sum = 0.0;
        g_npos    = 0;
        g_ticket  = 0u;
    }
}

// ---------------- launch -----------------------------------------------------
extern "C" void kernel_launch(void* const* d_in, const int* in_sizes, int n_in,
                              void* d_out, int out_size) {
    const float* cls_preds = (const float*)d_in[0];
    const float* box_preds = (const float*)d_in[1];
    const float* anchors   = (const float*)d_in[2];
    const float* tboxes    = (const float*)d_in[3];
    const int*   tlabels   = (const int*)d_in[4];
    float* out = (float*)d_out;

    acount_kernel<<<PREPG, PREPB>>>(anchors);
    prep_kernel<<<1, NUM_T>>>(tboxes);
    ascatter_kernel<<<PREPG, PREPB>>>(anchors);
    fused_kernel<<<MATCHB, BLK>>>(cls_preds, tlabels, box_preds,
                                  anchors, tboxes, out);
}

// round 13
// speedup vs baseline: 1.2000x; 1.2000x over previous
#include <cuda_runtime.h>
#include <cstdint>

#define NUM_A   98304
#define NUM_T   1024
#define NCLS    21
#define NLOGIT  (NUM_A * NCLS)
#define NVEC    (NLOGIT / 4)            // 516096

#define GB      32
#define CELLS   (GB * GB)

#define BLK     128
#define APT     2
#define WSPLIT  6
#define AGRP    (NUM_A / (BLK * APT))   // 384 anchor groups (256 anchors each)
#define MATCHB  (AGRP * WSPLIT)         // 2304 blocks
#define FSLICE  (NVEC / MATCHB)         // 224 float4 per block (exact)

#define PREPB   256
#define PREPG   (NUM_A / PREPB)         // 384

#define EPI_BLK  256
#define EPI_GRID (NUM_A / EPI_BLK)      // 384

typedef unsigned long long ull;

// ---------------- device scratch (zero-init; self-restoring) -----------------
__device__ float4   g_tbox_s[NUM_T];
__device__ int      g_tid_s[NUM_T];
__device__ int      g_toff[CELLS + 1];

__device__ int      g_acnt[CELLS];      // reset by last epi block
__device__ int      g_aoff[CELLS + 1];
__device__ int      g_acell[NUM_A];
__device__ int      g_arank[NUM_A];
__device__ float4   g_abox_s[NUM_A];
__device__ int      g_aid_s[NUM_A];

__device__ ull      g_akey[NUM_A];      // atomicMax; zeroed in ascatter
__device__ ull      g_tkey[NUM_T];      // atomicMax (sorted idx); reset by epi
__device__ double   g_cls_sum;          // reset by last epi block
__device__ int      g_npos;             // reset by last epi block
__device__ unsigned g_ticket;           // reset by last epi block

// fast negative-class focal: 0.75 * sigmoid(x)^2 * softplus(x); 3 MUFU ops
__device__ __forceinline__ float focal_neg(float x) {
    float u = exp2f(x * 1.4426950408889634f);
    float d = u + 1.0f;
    float q; asm("rcp.approx.f32 %0, %1;" : "=f"(q) : "f"(d));
    float lg = __log2f(d);
    float p  = u * q;
    return (0.75f * 0.6931471805599453f) * (p * p) * lg;
}

__device__ __forceinline__ int cell_of(float cx, float cy) {
    int bx = min(GB - 1, max(0, (int)(cx * (float)GB)));
    int by = min(GB - 1, max(0, (int)(cy * (float)GB)));
    return by * GB + bx;
}

__device__ __forceinline__ float sl1(float d) {
    float ad = fabsf(d);
    return (ad < 1.0f) ? 0.5f * d * d : ad - 0.5f;
}

// fast 1024-thread inclusive scan (3-phase shfl)
__device__ __forceinline__ int scan1024(int v, int tid, int* wsum) {
    int lane = tid & 31, wid = tid >> 5;
    #pragma unroll
    for (int o = 1; o < 32; o <<= 1) {
        int n = __shfl_up_sync(0xFFFFFFFFu, v, o);
        if (lane >= o) v += n;
    }
    if (lane == 31) wsum[wid] = v;
    __syncthreads();
    if (wid == 0) {
        int s = wsum[lane];
        #pragma unroll
        for (int o = 1; o < 32; o <<= 1) {
            int n = __shfl_up_sync(0xFFFFFFFFu, s, o);
            if (lane >= o) s += n;
        }
        wsum[lane] = s;
    }
    __syncthreads();
    return v + (wid > 0 ? wsum[wid - 1] : 0);
}

// ---------------- L1: anchor cell + rank -------------------------------------
__global__ void __launch_bounds__(PREPB) acount_kernel(
    const float* __restrict__ anchors)
{
    const int a = blockIdx.x * PREPB + threadIdx.x;
    float4 ab = ((const float4*)anchors)[a];
    int cell = cell_of(0.5f * (ab.x + ab.z), 0.5f * (ab.y + ab.w));
    g_acell[a] = cell;
    g_arank[a] = atomicAdd(&g_acnt[cell], 1);
}

// ---------------- L2: target CSR + anchor offset scan (1 block) --------------
__global__ void __launch_bounds__(NUM_T) prep_kernel(
    const float* __restrict__ tboxes)
{
    __shared__ int tcnt[CELLS];
    __shared__ int texcl[CELLS];
    __shared__ int wsum[32];
    const int tid = threadIdx.x;

    tcnt[tid] = 0;
    __syncthreads();

    float4 b = ((const float4*)tboxes)[tid];
    int cell = cell_of(0.5f * (b.x + b.z), 0.5f * (b.y + b.w));
    int rank = atomicAdd(&tcnt[cell], 1);
    __syncthreads();

    int incl = scan1024(tcnt[tid], tid, wsum);
    int excl = incl - tcnt[tid];
    g_toff[tid] = excl;
    texcl[tid] = excl;
    if (tid == 0) g_toff[CELLS] = NUM_T;
    __syncthreads();

    int pos = texcl[cell] + rank;
    g_tbox_s[pos] = b;
    g_tid_s[pos]  = tid;

    __syncthreads();
    int ai = scan1024(g_acnt[tid], tid, wsum);
    g_aoff[tid] = ai - g_acnt[tid];
    if (tid == 0) g_aoff[CELLS] = NUM_A;
}

// ---------------- L3: anchor scatter + g_akey zero ---------------------------
__global__ void __launch_bounds__(PREPB) ascatter_kernel(
    const float* __restrict__ anchors)
{
    const int a = blockIdx.x * PREPB + threadIdx.x;
    int pos = g_aoff[g_acell[a]] + g_arank[a];
    g_abox_s[pos] = ((const float4*)anchors)[a];
    g_aid_s[pos]  = a;
    g_akey[a]     = 0ULL;
}

// ---------------- L4: match (REDUX-aggregated atomics) + focal slice ---------
__global__ void __launch_bounds__(BLK, 10) fused_kernel(
    const float* __restrict__ cls_preds)
{
    const int tid  = threadIdx.x;
    const int grp  = blockIdx.x / WSPLIT;
    const int part = blockIdx.x % WSPLIT;

    const int sp0 = grp * (BLK * APT) + 2 * tid;   // adjacent sorted anchors
    const float4 ab0 = g_abox_s[sp0];
    const float4 ab1 = g_abox_s[sp0 + 1];
    const int orig0 = g_aid_s[sp0];
    const int orig1 = g_aid_s[sp0 + 1];

    const float aw0 = ab0.z - ab0.x, ah0 = ab0.w - ab0.y;
    const float aw1 = ab1.z - ab1.x, ah1 = ab1.w - ab1.y;
    const float area0 = aw0 * ah0;
    const float area1 = aw1 * ah1;

    const float acx0 = 0.5f * (ab0.x + ab0.z), acy0 = 0.5f * (ab0.y + ab0.w);
    const float acx1 = 0.5f * (ab1.x + ab1.z), acy1 = 0.5f * (ab1.y + ab1.w);
    const float Rx0 = 0.55f * fminf(aw0 * 2.2223f, 0.34f);
    const float Ry0 = 0.55f * fminf(ah0 * 2.2223f, 0.34f);
    const float Rx1 = 0.55f * fminf(aw1 * 2.2223f, 0.34f);
    const float Ry1 = 0.55f * fminf(ah1 * 2.2223f, 0.34f);
    float xlo = fminf(acx0 - Rx0, acx1 - Rx1);
    float xhi = fmaxf(acx0 + Rx0, acx1 + Rx1);
    float ylo = fminf(acy0 - Ry0, acy1 - Ry1);
    float yhi = fmaxf(acy0 + Ry0, acy1 + Ry1);
    int clo = max(0, (int)(xlo * (float)GB));
    int chi = min(GB - 1, (int)(xhi * (float)GB));
    int rlo = max(0, (int)(ylo * (float)GB));
    int rhi = min(GB - 1, (int)(yhi * (float)GB));

    int clo_w = __reduce_min_sync(0xFFFFFFFFu, (unsigned)clo);
    int chi_w = __reduce_max_sync(0xFFFFFFFFu, (unsigned)chi);
    int rlo_w = __reduce_min_sync(0xFFFFFFFFu, (unsigned)rlo);
    int rhi_w = __reduce_max_sync(0xFFFFFFFFu, (unsigned)rhi);

    int len = rhi_w - rlo_w + 1;
    int r0 = rlo_w + (len * part)       / WSPLIT;
    int r1 = rlo_w + (len * (part + 1)) / WSPLIT - 1;

    float bi0 = 0.0f, bS0 = 1.0f, bi1 = 0.0f, bS1 = 1.0f;
    int   bt0 = 0, bt1 = 0;

    for (int r = r0; r <= r1; ++r) {
        int j  = g_toff[(r << 5) + clo_w];
        int je = g_toff[(r << 5) + chi_w + 1];
        #pragma unroll 2
        for (; j < je; ++j) {
            float4 tb = __ldg(&g_tbox_s[j]);
            float ta = (tb.z - tb.x) * (tb.w - tb.y);

            float lx0 = fmaxf(ab0.x, tb.x), ly0 = fmaxf(ab0.y, tb.y);
            float rx0 = fminf(ab0.z, tb.z), ry0 = fminf(ab0.w, tb.w);
            float w0  = fmaxf(rx0 - lx0, 0.0f);
            float in0 = w0 * (ry0 - ly0);
            float S0  = area0 + ta;
            bool p0 = in0 * bS0 > bi0 * S0;
            if (p0) { bi0 = in0; bS0 = S0; bt0 = j; }
            bool c0 = in0 > 0.3103448f * S0;       // iou > 0.45

            float lx1 = fmaxf(ab1.x, tb.x), ly1 = fmaxf(ab1.y, tb.y);
            float rx1 = fminf(ab1.z, tb.z), ry1 = fminf(ab1.w, tb.w);
            float w1  = fmaxf(rx1 - lx1, 0.0f);
            float in1 = w1 * (ry1 - ly1);
            float S1  = area1 + ta;
            bool p1 = in1 * bS1 > bi1 * S1;
            if (p1) { bi1 = in1; bS1 = S1; bt1 = j; }
            bool c1 = in1 > 0.3103448f * S1;

            // REDUX-aggregated target-side max: 2 hardware reductions + 1 atomic
            if (__ballot_sync(0xFFFFFFFFu, c0 || c1)) {
                unsigned i0 = c0 ? __float_as_uint(__fdividef(in0, S0 - in0)) : 0u;
                unsigned i1 = c1 ? __float_as_uint(__fdividef(in1, S1 - in1)) : 0u;
                unsigned hi = __reduce_max_sync(0xFFFFFFFFu, i0 > i1 ? i0 : i1);
                // min original anchor among lanes achieving hi (first-max tiebreak)
                unsigned am = 0xFFFFFFFFu;
                if (c0 && i0 == hi) am = (unsigned)orig0;
                if (c1 && i1 == hi) am = min(am, (unsigned)orig1);
                am = __reduce_min_sync(0xFFFFFFFFu, am);
                if ((tid & 31) == 0)
                    atomicMax(&g_tkey[j],
                              ((ull)hi << 32) | (ull)(0xFFFFFFFFu - am));
            }
        }
    }

    {
        float iou0 = __fdividef(bi0, bS0 - bi0);
        atomicMax(&g_akey[orig0],
                  ((ull)__float_as_uint(iou0) << 32)
                  | (ull)(0xFFFFFFFFu - (unsigned)bt0));
        float iou1 = __fdividef(bi1, bS1 - bi1);
        atomicMax(&g_akey[orig1],
                  ((ull)__float_as_uint(iou1) << 32)
                  | (ull)(0xFFFFFFFFu - (unsigned)bt1));
    }

    // ---- uniform focal slice ------------------------------------------------
    {
        const float4* cp = (const float4*)cls_preds;
        const int lo = blockIdx.x * FSLICE;
        float acc = 0.0f;
        for (int i = lo + tid; i < lo + FSLICE; i += BLK) {
            float4 v = cp[i];
            acc += focal_neg(v.x) + focal_neg(v.y)
                 + focal_neg(v.z) + focal_neg(v.w);
        }
        #pragma unroll
        for (int o = 16; o > 0; o >>= 1)
            acc += __shfl_down_sync(0xFFFFFFFFu, acc, o);
        __shared__ float rs[4];
        if ((tid & 31) == 0) rs[tid >> 5] = acc;
        __syncthreads();
        if (tid == 0)
            atomicAdd(&g_cls_sum, (double)(rs[0] + rs[1] + rs[2] + rs[3]));
    }
}

// ---------------- L5: epilogue -----------------------------------------------
__global__ void __launch_bounds__(EPI_BLK) epilogue_kernel(
    const float* __restrict__ cls_preds,
    const int*   __restrict__ tlabels,
    const float* __restrict__ boxes_preds,
    const float* __restrict__ anchors,
    const float* __restrict__ tboxes,
    float* __restrict__ out)
{
    const int tid = threadIdx.x;
    const int a = blockIdx.x * EPI_BLK + tid;

    ull key = g_akey[a];
    float iou = __uint_as_float((unsigned)(key >> 32));
    float delta = 0.0f;
    int   np = 0;
    if (iou >= 0.5f) {
        np = 1;
        int ts = (int)(0xFFFFFFFFu - (unsigned)(key & 0xFFFFFFFFull));
        int L = tlabels[g_tid_s[ts]];          // sorted -> original target
        float x = cls_preds[(size_t)a * NCLS + L];
        float ax = fabsf(x);
        float ce = fmaxf(x, 0.0f) - x + log1pf(expf(-ax));
        float p  = 1.0f / (1.0f + expf(-x));
        float om = 1.0f - p;
        delta = 0.25f * om * om * ce - focal_neg(x);
    }
    #pragma unroll
    for (int o = 16; o > 0; o >>= 1) {
        delta += __shfl_down_sync(0xFFFFFFFFu, delta, o);
        np    += __shfl_down_sync(0xFFFFFFFFu, np,    o);
    }
    __shared__ float rs[8];
    __shared__ int   ri[8];
    if ((tid & 31) == 0) { rs[tid >> 5] = delta; ri[tid >> 5] = np; }
    __syncthreads();
    if (tid == 0) {
        float bs = 0.0f; int bn = 0;
        #pragma unroll
        for (int i = 0; i < 8; ++i) { bs += rs[i]; bn += ri[i]; }
        atomicAdd(&g_cls_sum, (double)bs);
        atomicAdd(&g_npos, bn);
    }

    __shared__ int is_last;
    __threadfence();
    if (tid == 0) is_last = (atomicAdd(&g_ticket, 1u) == EPI_GRID - 1);
    __syncthreads();
    if (!is_last) return;

    for (int i = tid; i < CELLS; i += EPI_BLK) g_acnt[i] = 0;  // restore

    float loss = 0.0f;
    int   nm = 0;
    for (int t = tid; t < NUM_T; t += EPI_BLK) {
        ull k = g_tkey[t];
        g_tkey[t] = 0ULL;                          // restore for next replay
        float tiou = __uint_as_float((unsigned)(k >> 32));
        if (tiou >= 0.5f) {
            nm++;
            int tor = g_tid_s[t];                  // sorted -> original
            unsigned aidx = 0xFFFFFFFFu - (unsigned)(k & 0xFFFFFFFFull);
            float4 abx = ((const float4*)anchors)[aidx];
            float4 tb  = ((const float4*)tboxes)[tor];
            float4 pr  = ((const float4*)boxes_preds)[aidx];
            float bw = tb.z - tb.x, bh = tb.w - tb.y;
            float bcx = tb.x + 0.5f * bw, bcy = tb.y + 0.5f * bh;
            float aww = abx.z - abx.x, ahh = abx.w - abx.y;
            float acx = abx.x + 0.5f * aww, acy = abx.y + 0.5f * ahh;
            float tx = (bcx - acx) / aww;
            float ty = (bcy - acy) / ahh;
            float tw = logf(fmaxf(bw, 1e-8f) / aww);
            float th = logf(fmaxf(bh, 1e-8f) / ahh);
            loss += sl1(pr.x - tx) + sl1(pr.y - ty)
                  + sl1(pr.z - tw) + sl1(pr.w - th);
        }
    }
    #pragma unroll
    for (int o = 16; o > 0; o >>= 1) {
        loss += __shfl_down_sync(0xFFFFFFFFu, loss, o);
        nm   += __shfl_down_sync(0xFFFFFFFFu, nm,   o);
    }
    __shared__ float frs[8];
    __shared__ int   frm[8];
    if ((tid & 31) == 0) { frs[tid >> 5] = loss; frm[tid >> 5] = nm; }
    __syncthreads();
    if (tid == 0) {
        float total = 0.0f; int tm = 0;
        #pragma unroll
        for (int i = 0; i < 8; ++i) { total += frs[i]; tm += frm[i]; }
        double cls_total = atomicAdd(&g_cls_sum, 0.0);
        int    npos      = atomicAdd(&g_npos, 0);
        double n_match   = (tm > 0) ? (double)tm : 1.0;
        double cls = cls_total / (double)npos;
        double reg = (double)total / (n_match * 4.0);
        out[0] = (float)(cls + reg);
        out[1] = (float)cls;
        out[2] = (float)reg;
        g_cls_sum = 0.0;
        g_npos    = 0;
        g_ticket  = 0u;
    }
}

// ---------------- launch -----------------------------------------------------
extern "C" void kernel_launch(void* const* d_in, const int* in_sizes, int n_in,
                              void* d_out, int out_size) {
    const float* cls_preds = (const float*)d_in[0];
    const float* box_preds = (const float*)d_in[1];
    const float* anchors   = (const float*)d_in[2];
    const float* tboxes    = (const float*)d_in[3];
    const int*   tlabels   = (const int*)d_in[4];
    float* out = (float*)d_out;

    acount_kernel<<<PREPG, PREPB>>>(anchors);
    prep_kernel<<<1, NUM_T>>>(tboxes);
    ascatter_kernel<<<PREPG, PREPB>>>(anchors);
    fused_kernel<<<MATCHB, BLK>>>(cls_preds);
    epilogue_kernel<<<EPI_GRID, EPI_BLK>>>(cls_preds, tlabels, box_preds,
                                           anchors, tboxes, out);
}

// round 14
// speedup vs baseline: 1.3002x; 1.0835x over previous
#include <cuda_runtime.h>
#include <cstdint>

#define NUM_A   98304
#define NUM_T   1024
#define NCLS    21
#define NLOGIT  (NUM_A * NCLS)
#define NVEC    (NLOGIT / 4)            // 516096

#define GB      32
#define CELLS   (GB * GB)

#define BLK     128
#define APT     2
#define WSPLIT  6
#define AGRP    (NUM_A / (BLK * APT))   // 384 anchor groups (256 anchors each)
#define MATCHB  (AGRP * WSPLIT)         // 2304 blocks
#define FSLICE  (NVEC / MATCHB)         // 224 float4 per block (exact)

#define PREPB   256
#define PREPG   (NUM_A / PREPB)         // 384

#define EPI_BLK  256
#define EPI_GRID (NUM_A / EPI_BLK)      // 384

typedef unsigned long long ull;

// ---------------- device scratch (zero-init; self-restoring) -----------------
__device__ float4   g_tbox_s[NUM_T];
__device__ int      g_tid_s[NUM_T];
__device__ int      g_toff[CELLS + 1];

__device__ int      g_acnt[CELLS];      // reset by last epi block
__device__ int      g_aoff[CELLS + 1];
__device__ int      g_acell[NUM_A];
__device__ int      g_arank[NUM_A];
__device__ float4   g_abox_s[NUM_A];
__device__ int      g_aid_s[NUM_A];

__device__ ull      g_akey[NUM_A];      // atomicMax; zeroed in ascatter
__device__ ull      g_tkey[NUM_T];      // atomicMax (sorted idx); reset by epi
__device__ double   g_cls_sum;          // reset by last epi block
__device__ int      g_npos;             // reset by last epi block
__device__ unsigned g_ticket;           // reset by last epi block

// fast negative-class focal: 0.75 * sigmoid(x)^2 * softplus(x); 3 MUFU ops
__device__ __forceinline__ float focal_neg(float x) {
    float u = exp2f(x * 1.4426950408889634f);
    float d = u + 1.0f;
    float q; asm("rcp.approx.f32 %0, %1;" : "=f"(q) : "f"(d));
    float lg = __log2f(d);
    float p  = u * q;
    return (0.75f * 0.6931471805599453f) * (p * p) * lg;
}

__device__ __forceinline__ int cell_of(float cx, float cy) {
    int bx = min(GB - 1, max(0, (int)(cx * (float)GB)));
    int by = min(GB - 1, max(0, (int)(cy * (float)GB)));
    return by * GB + bx;
}

__device__ __forceinline__ float sl1(float d) {
    float ad = fabsf(d);
    return (ad < 1.0f) ? 0.5f * d * d : ad - 0.5f;
}

// fast 1024-thread inclusive scan (3-phase shfl)
__device__ __forceinline__ int scan1024(int v, int tid, int* wsum) {
    int lane = tid & 31, wid = tid >> 5;
    #pragma unroll
    for (int o = 1; o < 32; o <<= 1) {
        int n = __shfl_up_sync(0xFFFFFFFFu, v, o);
        if (lane >= o) v += n;
    }
    if (lane == 31) wsum[wid] = v;
    __syncthreads();
    if (wid == 0) {
        int s = wsum[lane];
        #pragma unroll
        for (int o = 1; o < 32; o <<= 1) {
            int n = __shfl_up_sync(0xFFFFFFFFu, s, o);
            if (lane >= o) s += n;
        }
        wsum[lane] = s;
    }
    __syncthreads();
    return v + (wid > 0 ? wsum[wid - 1] : 0);
}

// ---------------- L1: anchor cell + rank -------------------------------------
__global__ void __launch_bounds__(PREPB) acount_kernel(
    const float* __restrict__ anchors)
{
    const int a = blockIdx.x * PREPB + threadIdx.x;
    float4 ab = ((const float4*)anchors)[a];
    int cell = cell_of(0.5f * (ab.x + ab.z), 0.5f * (ab.y + ab.w));
    g_acell[a] = cell;
    g_arank[a] = atomicAdd(&g_acnt[cell], 1);
}

// ---------------- L2: target CSR + anchor offset scan (1 block) --------------
__global__ void __launch_bounds__(NUM_T) prep_kernel(
    const float* __restrict__ tboxes)
{
    __shared__ int tcnt[CELLS];
    __shared__ int texcl[CELLS];
    __shared__ int wsum[32];
    const int tid = threadIdx.x;

    tcnt[tid] = 0;
    __syncthreads();

    float4 b = ((const float4*)tboxes)[tid];
    int cell = cell_of(0.5f * (b.x + b.z), 0.5f * (b.y + b.w));
    int rank = atomicAdd(&tcnt[cell], 1);
    __syncthreads();

    int incl = scan1024(tcnt[tid], tid, wsum);
    int excl = incl - tcnt[tid];
    g_toff[tid] = excl;
    texcl[tid] = excl;
    if (tid == 0) g_toff[CELLS] = NUM_T;
    __syncthreads();

    int pos = texcl[cell] + rank;
    g_tbox_s[pos] = b;
    g_tid_s[pos]  = tid;

    __syncthreads();
    int ai = scan1024(g_acnt[tid], tid, wsum);
    g_aoff[tid] = ai - g_acnt[tid];
    if (tid == 0) g_aoff[CELLS] = NUM_A;
}

// ---------------- L3: anchor scatter + g_akey zero ---------------------------
__global__ void __launch_bounds__(PREPB) ascatter_kernel(
    const float* __restrict__ anchors)
{
    const int a = blockIdx.x * PREPB + threadIdx.x;
    int pos = g_aoff[g_acell[a]] + g_arank[a];
    g_abox_s[pos] = ((const float4*)anchors)[a];
    g_aid_s[pos]  = a;
    g_akey[a]     = 0ULL;
}

// ---------------- L4: match (gated best-tracking + REDUX atomics) ------------
__global__ void __launch_bounds__(BLK, 10) fused_kernel(
    const float* __restrict__ cls_preds)
{
    const int tid  = threadIdx.x;
    const int grp  = blockIdx.x / WSPLIT;
    const int part = blockIdx.x % WSPLIT;

    const int sp0 = grp * (BLK * APT) + 2 * tid;   // adjacent sorted anchors
    const float4 ab0 = g_abox_s[sp0];
    const float4 ab1 = g_abox_s[sp0 + 1];
    const int orig0 = g_aid_s[sp0];
    const int orig1 = g_aid_s[sp0 + 1];

    const float aw0 = ab0.z - ab0.x, ah0 = ab0.w - ab0.y;
    const float aw1 = ab1.z - ab1.x, ah1 = ab1.w - ab1.y;
    const float area0 = aw0 * ah0;
    const float area1 = aw1 * ah1;

    const float acx0 = 0.5f * (ab0.x + ab0.z), acy0 = 0.5f * (ab0.y + ab0.w);
    const float acx1 = 0.5f * (ab1.x + ab1.z), acy1 = 0.5f * (ab1.y + ab1.w);
    const float Rx0 = 0.55f * fminf(aw0 * 2.2223f, 0.34f);
    const float Ry0 = 0.55f * fminf(ah0 * 2.2223f, 0.34f);
    const float Rx1 = 0.55f * fminf(aw1 * 2.2223f, 0.34f);
    const float Ry1 = 0.55f * fminf(ah1 * 2.2223f, 0.34f);
    float xlo = fminf(acx0 - Rx0, acx1 - Rx1);
    float xhi = fmaxf(acx0 + Rx0, acx1 + Rx1);
    float ylo = fminf(acy0 - Ry0, acy1 - Ry1);
    float yhi = fmaxf(acy0 + Ry0, acy1 + Ry1);
    int clo = max(0, (int)(xlo * (float)GB));
    int chi = min(GB - 1, (int)(xhi * (float)GB));
    int rlo = max(0, (int)(ylo * (float)GB));
    int rhi = min(GB - 1, (int)(yhi * (float)GB));

    int clo_w = __reduce_min_sync(0xFFFFFFFFu, (unsigned)clo);
    int chi_w = __reduce_max_sync(0xFFFFFFFFu, (unsigned)chi);
    int rlo_w = __reduce_min_sync(0xFFFFFFFFu, (unsigned)rlo);
    int rhi_w = __reduce_max_sync(0xFFFFFFFFu, (unsigned)rhi);

    int len = rhi_w - rlo_w + 1;
    int r0 = rlo_w + (len * part)       / WSPLIT;
    int r1 = rlo_w + (len * (part + 1)) / WSPLIT - 1;

    // best tracked ONLY among candidates with iou > 0.45: valid because the
    // anchor-side argmax is consumed only when max_iou >= 0.5 (> 0.45).
    float bf0 = 0.0f, bf1 = 0.0f;
    int   bt0 = 0, bt1 = 0;

    for (int r = r0; r <= r1; ++r) {
        int j  = g_toff[(r << 5) + clo_w];
        int je = g_toff[(r << 5) + chi_w + 1];
        #pragma unroll 2
        for (; j < je; ++j) {
            float4 tb = __ldg(&g_tbox_s[j]);
            float ta = (tb.z - tb.x) * (tb.w - tb.y);

            float lx0 = fmaxf(ab0.x, tb.x), ly0 = fmaxf(ab0.y, tb.y);
            float rx0 = fminf(ab0.z, tb.z), ry0 = fminf(ab0.w, tb.w);
            float w0  = fmaxf(rx0 - lx0, 0.0f);
            float in0 = w0 * (ry0 - ly0);
            float S0  = area0 + ta;
            bool c0 = in0 > 0.3103448f * S0;       // iou > 0.45

            float lx1 = fmaxf(ab1.x, tb.x), ly1 = fmaxf(ab1.y, tb.y);
            float rx1 = fminf(ab1.z, tb.z), ry1 = fminf(ab1.w, tb.w);
            float w1  = fmaxf(rx1 - lx1, 0.0f);
            float in1 = w1 * (ry1 - ly1);
            float S1  = area1 + ta;
            bool c1 = in1 > 0.3103448f * S1;

            if (__ballot_sync(0xFFFFFFFFu, c0 || c1)) {
                unsigned i0 = 0u, i1 = 0u;
                if (c0) {
                    float f = __fdividef(in0, S0 - in0);
                    if (f > bf0) { bf0 = f; bt0 = j; }   // strict >: first max
                    i0 = __float_as_uint(f);
                }
                if (c1) {
                    float f = __fdividef(in1, S1 - in1);
                    if (f > bf1) { bf1 = f; bt1 = j; }
                    i1 = __float_as_uint(f);
                }
                unsigned hi = __reduce_max_sync(0xFFFFFFFFu, i0 > i1 ? i0 : i1);
                unsigned am = 0xFFFFFFFFu;
                if (c0 && i0 == hi) am = (unsigned)orig0;
                if (c1 && i1 == hi) am = min(am, (unsigned)orig1);
                am = __reduce_min_sync(0xFFFFFFFFu, am);
                if ((tid & 31) == 0)
                    atomicMax(&g_tkey[j],
                              ((ull)hi << 32) | (ull)(0xFFFFFFFFu - am));
            }
        }
    }

    atomicMax(&g_akey[orig0],
              ((ull)__float_as_uint(bf0) << 32)
              | (ull)(0xFFFFFFFFu - (unsigned)bt0));
    atomicMax(&g_akey[orig1],
              ((ull)__float_as_uint(bf1) << 32)
              | (ull)(0xFFFFFFFFu - (unsigned)bt1));

    // ---- uniform focal slice ------------------------------------------------
    {
        const float4* cp = (const float4*)cls_preds;
        const int lo = blockIdx.x * FSLICE;
        float acc = 0.0f;
        for (int i = lo + tid; i < lo + FSLICE; i += BLK) {
            float4 v = cp[i];
            acc += focal_neg(v.x) + focal_neg(v.y)
                 + focal_neg(v.z) + focal_neg(v.w);
        }
        #pragma unroll
        for (int o = 16; o > 0; o >>= 1)
            acc += __shfl_down_sync(0xFFFFFFFFu, acc, o);
        __shared__ float rs[4];
        if ((tid & 31) == 0) rs[tid >> 5] = acc;
        __syncthreads();
        if (tid == 0)
            atomicAdd(&g_cls_sum, (double)(rs[0] + rs[1] + rs[2] + rs[3]));
    }
}

// ---------------- L5: epilogue -----------------------------------------------
__global__ void __launch_bounds__(EPI_BLK) epilogue_kernel(
    const float* __restrict__ cls_preds,
    const int*   __restrict__ tlabels,
    const float* __restrict__ boxes_preds,
    const float* __restrict__ anchors,
    const float* __restrict__ tboxes,
    float* __restrict__ out)
{
    const int tid = threadIdx.x;
    const int a = blockIdx.x * EPI_BLK + tid;

    ull key = g_akey[a];
    float iou = __uint_as_float((unsigned)(key >> 32));
    float delta = 0.0f;
    int   np = 0;
    if (iou >= 0.5f) {
        np = 1;
        int ts = (int)(0xFFFFFFFFu - (unsigned)(key & 0xFFFFFFFFull));
        int L = tlabels[g_tid_s[ts]];          // sorted -> original target
        float x = cls_preds[(size_t)a * NCLS + L];
        float ax = fabsf(x);
        float ce = fmaxf(x, 0.0f) - x + log1pf(expf(-ax));
        float p  = 1.0f / (1.0f + expf(-x));
        float om = 1.0f - p;
        delta = 0.25f * om * om * ce - focal_neg(x);
    }
    #pragma unroll
    for (int o = 16; o > 0; o >>= 1) {
        delta += __shfl_down_sync(0xFFFFFFFFu, delta, o);
        np    += __shfl_down_sync(0xFFFFFFFFu, np,    o);
    }
    __shared__ float rs[8];
    __shared__ int   ri[8];
    if ((tid & 31) == 0) { rs[tid >> 5] = delta; ri[tid >> 5] = np; }
    __syncthreads();
    if (tid == 0) {
        float bs = 0.0f; int bn = 0;
        #pragma unroll
        for (int i = 0; i < 8; ++i) { bs += rs[i]; bn += ri[i]; }
        atomicAdd(&g_cls_sum, (double)bs);
        atomicAdd(&g_npos, bn);
    }

    __shared__ int is_last;
    __threadfence();
    if (tid == 0) is_last = (atomicAdd(&g_ticket, 1u) == EPI_GRID - 1);
    __syncthreads();
    if (!is_last) return;

    for (int i = tid; i < CELLS; i += EPI_BLK) g_acnt[i] = 0;  // restore

    float loss = 0.0f;
    int   nm = 0;
    for (int t = tid; t < NUM_T; t += EPI_BLK) {
        ull k = g_tkey[t];
        g_tkey[t] = 0ULL;                          // restore for next replay
        float tiou = __uint_as_float((unsigned)(k >> 32));
        if (tiou >= 0.5f) {
            nm++;
            int tor = g_tid_s[t];                  // sorted -> original
            unsigned aidx = 0xFFFFFFFFu - (unsigned)(k & 0xFFFFFFFFull);
            float4 abx = ((const float4*)anchors)[aidx];
            float4 tb  = ((const float4*)tboxes)[tor];
            float4 pr  = ((const float4*)boxes_preds)[aidx];
            float bw = tb.z - tb.x, bh = tb.w - tb.y;
            float bcx = tb.x + 0.5f * bw, bcy = tb.y + 0.5f * bh;
            float aww = abx.z - abx.x, ahh = abx.w - abx.y;
            float acx = abx.x + 0.5f * aww, acy = abx.y + 0.5f * ahh;
            float tx = (bcx - acx) / aww;
            float ty = (bcy - acy) / ahh;
            float tw = logf(fmaxf(bw, 1e-8f) / aww);
            float th = logf(fmaxf(bh, 1e-8f) / ahh);
            loss += sl1(pr.x - tx) + sl1(pr.y - ty)
                  + sl1(pr.z - tw) + sl1(pr.w - th);
        }
    }
    #pragma unroll
    for (int o = 16; o > 0; o >>= 1) {
        loss += __shfl_down_sync(0xFFFFFFFFu, loss, o);
        nm   += __shfl_down_sync(0xFFFFFFFFu, nm,   o);
    }
    __shared__ float frs[8];
    __shared__ int   frm[8];
    if ((tid & 31) == 0) { frs[tid >> 5] = loss; frm[tid >> 5] = nm; }
    __syncthreads();
    if (tid == 0) {
        float total = 0.0f; int tm = 0;
        #pragma unroll
        for (int i = 0; i < 8; ++i) { total += frs[i]; tm += frm[i]; }
        double cls_total = atomicAdd(&g_cls_sum, 0.0);
        int    npos      = atomicAdd(&g_npos, 0);
        double n_match   = (tm > 0) ? (double)tm : 1.0;
        double cls = cls_total / (double)npos;
        double reg = (double)total / (n_match * 4.0);
        out[0] = (float)(cls + reg);
        out[1] = (float)cls;
        out[2] = (float)reg;
        g_cls_sum = 0.0;
        g_npos    = 0;
        g_ticket  = 0u;
    }
}

// ---------------- launch -----------------------------------------------------
extern "C" void kernel_launch(void* const* d_in, const int* in_sizes, int n_in,
                              void* d_out, int out_size) {
    const float* cls_preds = (const float*)d_in[0];
    const float* box_preds = (const float*)d_in[1];
    const float* anchors   = (const float*)d_in[2];
    const float* tboxes    = (const float*)d_in[3];
    const int*   tlabels   = (const int*)d_in[4];
    float* out = (float*)d_out;

    acount_kernel<<<PREPG, PREPB>>>(anchors);
    prep_kernel<<<1, NUM_T>>>(tboxes);
    ascatter_kernel<<<PREPG, PREPB>>>(anchors);
    fused_kernel<<<MATCHB, BLK>>>(cls_preds);
    epilogue_kernel<<<EPI_GRID, EPI_BLK>>>(cls_preds, tlabels, box_preds,
                                           anchors, tboxes, out);
}

// round 15
// speedup vs baseline: 1.3922x; 1.0708x over previous
#include <cuda_runtime.h>
#include <cstdint>

#define NUM_A   98304
#define NUM_T   1024
#define NCLS    21
#define NLOGIT  (NUM_A * NCLS)
#define NVEC    (NLOGIT / 4)            // 516096

#define GB      32
#define CELLS   (GB * GB)

#define BLK     128
#define APT     2
#define WSPLIT  8
#define AGRP    (NUM_A / (BLK * APT))   // 384 anchor groups (256 anchors each)
#define MATCHB  (AGRP * WSPLIT)         // 3072 blocks
#define FSLICE  (NVEC / MATCHB)         // 168 float4 per block (exact)

#define PREPB   256
#define PREPG   (NUM_A / PREPB)         // 384

#define EPI_BLK  256
#define EPI_GRID (NUM_A / EPI_BLK)      // 384

typedef unsigned long long ull;

// ---------------- device scratch (zero-init; self-restoring) -----------------
__device__ float4   g_tbox_s[NUM_T];
__device__ int      g_tid_s[NUM_T];
__device__ int      g_toff[CELLS + 1];

__device__ int      g_acnt[CELLS];      // reset by last epi block
__device__ int      g_aoff[CELLS + 1];
__device__ int      g_acell[NUM_A];
__device__ int      g_arank[NUM_A];
__device__ float4   g_abox_s[NUM_A];
__device__ int      g_aid_s[NUM_A];

__device__ ull      g_akey[NUM_A];      // atomicMax; zeroed in scatter
__device__ ull      g_tkey[NUM_T];      // atomicMax (sorted idx); reset by epi
__device__ unsigned g_scan_tk;          // acount ticket; reset by its consumer
__device__ double   g_cls_sum;          // reset by last epi block
__device__ int      g_npos;             // reset by last epi block
__device__ unsigned g_ticket;           // reset by last epi block

// fast negative-class focal: 0.75 * sigmoid(x)^2 * softplus(x); 3 MUFU ops
__device__ __forceinline__ float focal_neg(float x) {
    float u = exp2f(x * 1.4426950408889634f);
    float d = u + 1.0f;
    float q; asm("rcp.approx.f32 %0, %1;" : "=f"(q) : "f"(d));
    float lg = __log2f(d);
    float p  = u * q;
    return (0.75f * 0.6931471805599453f) * (p * p) * lg;
}

__device__ __forceinline__ int cell_of(float cx, float cy) {
    int bx = min(GB - 1, max(0, (int)(cx * (float)GB)));
    int by = min(GB - 1, max(0, (int)(cy * (float)GB)));
    return by * GB + bx;
}

__device__ __forceinline__ float sl1(float d) {
    float ad = fabsf(d);
    return (ad < 1.0f) ? 0.5f * d * d : ad - 0.5f;
}

// 256-thread inclusive scan of per-thread value; returns inclusive sum
__device__ __forceinline__ int scan256(int v, int tid, int* wsum) {
    int lane = tid & 31, wid = tid >> 5;
    #pragma unroll
    for (int o = 1; o < 32; o <<= 1) {
        int n = __shfl_up_sync(0xFFFFFFFFu, v, o);
        if (lane >= o) v += n;
    }
    if (lane == 31) wsum[wid] = v;
    __syncthreads();
    if (wid == 0 && lane < 8) {
        int s = wsum[lane];
        #pragma unroll
        for (int o = 1; o < 8; o <<= 1) {
            int n = __shfl_up_sync(0xFFu, s, o);
            if (lane >= o) s += n;
        }
        wsum[lane] = s;
    }
    __syncthreads();
    return v + (wid > 0 ? wsum[wid - 1] : 0);
}

// ---------------- K1: anchor cell+rank; last block scans cell offsets --------
__global__ void __launch_bounds__(PREPB) acount_kernel(
    const float* __restrict__ anchors)
{
    const int tid = threadIdx.x;
    const int a = blockIdx.x * PREPB + tid;
    float4 ab = ((const float4*)anchors)[a];
    int cell = cell_of(0.5f * (ab.x + ab.z), 0.5f * (ab.y + ab.w));
    g_acell[a] = cell;
    g_arank[a] = atomicAdd(&g_acnt[cell], 1);

    // last block performs the 1024-cell exclusive scan (4 cells per thread)
    __shared__ int is_last;
    __threadfence();
    if (tid == 0) is_last = (atomicAdd(&g_scan_tk, 1u) == PREPG - 1);
    __syncthreads();
    if (!is_last) return;

    __shared__ int wsum[32];
    int c0 = g_acnt[4 * tid + 0];
    int c1 = g_acnt[4 * tid + 1];
    int c2 = g_acnt[4 * tid + 2];
    int c3 = g_acnt[4 * tid + 3];
    int incl = scan256(c0 + c1 + c2 + c3, tid, wsum);
    int e = incl - (c0 + c1 + c2 + c3);
    g_aoff[4 * tid + 0] = e;
    g_aoff[4 * tid + 1] = e + c0;
    g_aoff[4 * tid + 2] = e + c0 + c1;
    g_aoff[4 * tid + 3] = e + c0 + c1 + c2;
    if (tid == PREPB - 1) g_aoff[CELLS] = NUM_A;
    if (tid == 0) g_scan_tk = 0u;               // restore for next replay
}

// ---------------- K2: anchor scatter (384 blocks) + target CSR (block 384) ---
__global__ void __launch_bounds__(PREPB) scatter_kernel(
    const float* __restrict__ anchors,
    const float* __restrict__ tboxes)
{
    const int tid = threadIdx.x;

    if (blockIdx.x < PREPG) {
        const int a = blockIdx.x * PREPB + tid;
        int pos = g_aoff[g_acell[a]] + g_arank[a];
        g_abox_s[pos] = ((const float4*)anchors)[a];
        g_aid_s[pos]  = a;
        g_akey[a]     = 0ULL;
        return;
    }

    // ---- target CSR with 256 threads (4 targets per thread) ----------------
    __shared__ int tcnt[CELLS];
    __shared__ int texcl[CELLS];
    __shared__ int wsum[32];
    #pragma unroll
    for (int i = 0; i < 4; ++i) tcnt[tid + 256 * i] = 0;
    __syncthreads();

    float4 tb[4]; int tc[4], tr[4];
    #pragma unroll
    for (int i = 0; i < 4; ++i) {
        int t = tid + 256 * i;
        tb[i] = ((const float4*)tboxes)[t];
        tc[i] = cell_of(0.5f * (tb[i].x + tb[i].z), 0.5f * (tb[i].y + tb[i].w));
        tr[i] = atomicAdd(&tcnt[tc[i]], 1);
    }
    __syncthreads();

    int c0 = tcnt[4 * tid + 0];
    int c1 = tcnt[4 * tid + 1];
    int c2 = tcnt[4 * tid + 2];
    int c3 = tcnt[4 * tid + 3];
    int incl = scan256(c0 + c1 + c2 + c3, tid, wsum);
    int e = incl - (c0 + c1 + c2 + c3);
    texcl[4 * tid + 0] = e;
    texcl[4 * tid + 1] = e + c0;
    texcl[4 * tid + 2] = e + c0 + c1;
    texcl[4 * tid + 3] = e + c0 + c1 + c2;
    g_toff[4 * tid + 0] = texcl[4 * tid + 0];
    g_toff[4 * tid + 1] = texcl[4 * tid + 1];
    g_toff[4 * tid + 2] = texcl[4 * tid + 2];
    g_toff[4 * tid + 3] = texcl[4 * tid + 3];
    if (tid == PREPB - 1) g_toff[CELLS] = NUM_T;
    __syncthreads();

    #pragma unroll
    for (int i = 0; i < 4; ++i) {
        int t = tid + 256 * i;
        int pos = texcl[tc[i]] + tr[i];
        g_tbox_s[pos] = tb[i];
        g_tid_s[pos]  = t;
    }
}

// ---------------- K3: match (gated best-tracking + REDUX atomics) ------------
__global__ void __launch_bounds__(BLK, 10) fused_kernel(
    const float* __restrict__ cls_preds)
{
    const int tid  = threadIdx.x;
    const int grp  = blockIdx.x / WSPLIT;
    const int part = blockIdx.x % WSPLIT;

    const int sp0 = grp * (BLK * APT) + 2 * tid;   // adjacent sorted anchors
    const float4 ab0 = g_abox_s[sp0];
    const float4 ab1 = g_abox_s[sp0 + 1];
    const int orig0 = g_aid_s[sp0];
    const int orig1 = g_aid_s[sp0 + 1];

    const float aw0 = ab0.z - ab0.x, ah0 = ab0.w - ab0.y;
    const float aw1 = ab1.z - ab1.x, ah1 = ab1.w - ab1.y;
    const float area0 = aw0 * ah0;
    const float area1 = aw1 * ah1;

    const float acx0 = 0.5f * (ab0.x + ab0.z), acy0 = 0.5f * (ab0.y + ab0.w);
    const float acx1 = 0.5f * (ab1.x + ab1.z), acy1 = 0.5f * (ab1.y + ab1.w);
    const float Rx0 = 0.55f * fminf(aw0 * 2.2223f, 0.34f);
    const float Ry0 = 0.55f * fminf(ah0 * 2.2223f, 0.34f);
    const float Rx1 = 0.55f * fminf(aw1 * 2.2223f, 0.34f);
    const float Ry1 = 0.55f * fminf(ah1 * 2.2223f, 0.34f);
    float xlo = fminf(acx0 - Rx0, acx1 - Rx1);
    float xhi = fmaxf(acx0 + Rx0, acx1 + Rx1);
    float ylo = fminf(acy0 - Ry0, acy1 - Ry1);
    float yhi = fmaxf(acy0 + Ry0, acy1 + Ry1);
    int clo = max(0, (int)(xlo * (float)GB));
    int chi = min(GB - 1, (int)(xhi * (float)GB));
    int rlo = max(0, (int)(ylo * (float)GB));
    int rhi = min(GB - 1, (int)(yhi * (float)GB));

    int clo_w = __reduce_min_sync(0xFFFFFFFFu, (unsigned)clo);
    int chi_w = __reduce_max_sync(0xFFFFFFFFu, (unsigned)chi);
    int rlo_w = __reduce_min_sync(0xFFFFFFFFu, (unsigned)rlo);
    int rhi_w = __reduce_max_sync(0xFFFFFFFFu, (unsigned)rhi);

    int len = rhi_w - rlo_w + 1;
    int r0 = rlo_w + (len * part)       / WSPLIT;
    int r1 = rlo_w + (len * (part + 1)) / WSPLIT - 1;

    // best tracked ONLY among candidates with iou > 0.45: valid because the
    // anchor-side argmax is consumed only when max_iou >= 0.5 (> 0.45).
    float bf0 = 0.0f, bf1 = 0.0f;
    int   bt0 = 0, bt1 = 0;

    for (int r = r0; r <= r1; ++r) {
        int j  = g_toff[(r << 5) + clo_w];
        int je = g_toff[(r << 5) + chi_w + 1];
        #pragma unroll 2
        for (; j < je; ++j) {
            float4 tb = __ldg(&g_tbox_s[j]);
            float ta = (tb.z - tb.x) * (tb.w - tb.y);

            float lx0 = fmaxf(ab0.x, tb.x), ly0 = fmaxf(ab0.y, tb.y);
            float rx0 = fminf(ab0.z, tb.z), ry0 = fminf(ab0.w, tb.w);
            float w0  = fmaxf(rx0 - lx0, 0.0f);
            float in0 = w0 * (ry0 - ly0);
            float S0  = area0 + ta;
            bool c0 = in0 > 0.3103448f * S0;       // iou > 0.45

            float lx1 = fmaxf(ab1.x, tb.x), ly1 = fmaxf(ab1.y, tb.y);
            float rx1 = fminf(ab1.z, tb.z), ry1 = fminf(ab1.w, tb.w);
            float w1  = fmaxf(rx1 - lx1, 0.0f);
            float in1 = w1 * (ry1 - ly1);
            float S1  = area1 + ta;
            bool c1 = in1 > 0.3103448f * S1;

            if (__ballot_sync(0xFFFFFFFFu, c0 || c1)) {
                unsigned i0 = 0u, i1 = 0u;
                if (c0) {
                    float f = __fdividef(in0, S0 - in0);
                    if (f > bf0) { bf0 = f; bt0 = j; }   // strict >: first max
                    i0 = __float_as_uint(f);
                }
                if (c1) {
                    float f = __fdividef(in1, S1 - in1);
                    if (f > bf1) { bf1 = f; bt1 = j; }
                    i1 = __float_as_uint(f);
                }
                unsigned hi = __reduce_max_sync(0xFFFFFFFFu, i0 > i1 ? i0 : i1);
                unsigned am = 0xFFFFFFFFu;
                if (c0 && i0 == hi) am = (unsigned)orig0;
                if (c1 && i1 == hi) am = min(am, (unsigned)orig1);
                am = __reduce_min_sync(0xFFFFFFFFu, am);
                if ((tid & 31) == 0)
                    atomicMax(&g_tkey[j],
                              ((ull)hi << 32) | (ull)(0xFFFFFFFFu - am));
            }
        }
    }

    atomicMax(&g_akey[orig0],
              ((ull)__float_as_uint(bf0) << 32)
              | (ull)(0xFFFFFFFFu - (unsigned)bt0));
    atomicMax(&g_akey[orig1],
              ((ull)__float_as_uint(bf1) << 32)
              | (ull)(0xFFFFFFFFu - (unsigned)bt1));

    // ---- uniform focal slice ------------------------------------------------
    {
        const float4* cp = (const float4*)cls_preds;
        const int lo = blockIdx.x * FSLICE;
        float acc = 0.0f;
        for (int i = lo + tid; i < lo + FSLICE; i += BLK) {
            float4 v = cp[i];
            acc += focal_neg(v.x) + focal_neg(v.y)
                 + focal_neg(v.z) + focal_neg(v.w);
        }
        #pragma unroll
        for (int o = 16; o > 0; o >>= 1)
            acc += __shfl_down_sync(0xFFFFFFFFu, acc, o);
        __shared__ float rs[4];
        if ((tid & 31) == 0) rs[tid >> 5] = acc;
        __syncthreads();
        if (tid == 0)
            atomicAdd(&g_cls_sum, (double)(rs[0] + rs[1] + rs[2] + rs[3]));
    }
}

// ---------------- K4: epilogue -----------------------------------------------
__global__ void __launch_bounds__(EPI_BLK) epilogue_kernel(
    const float* __restrict__ cls_preds,
    const int*   __restrict__ tlabels,
    const float* __restrict__ boxes_preds,
    const float* __restrict__ anchors,
    const float* __restrict__ tboxes,
    float* __restrict__ out)
{
    const int tid = threadIdx.x;
    const int a = blockIdx.x * EPI_BLK + tid;

    ull key = g_akey[a];
    float iou = __uint_as_float((unsigned)(key >> 32));
    float delta = 0.0f;
    int   np = 0;
    if (iou >= 0.5f) {
        np = 1;
        int ts = (int)(0xFFFFFFFFu - (unsigned)(key & 0xFFFFFFFFull));
        int L = tlabels[g_tid_s[ts]];          // sorted -> original target
        float x = cls_preds[(size_t)a * NCLS + L];
        float ax = fabsf(x);
        float ce = fmaxf(x, 0.0f) - x + log1pf(expf(-ax));
        float p  = 1.0f / (1.0f + expf(-x));
        float om = 1.0f - p;
        delta = 0.25f * om * om * ce - focal_neg(x);
    }
    #pragma unroll
    for (int o = 16; o > 0; o >>= 1) {
        delta += __shfl_down_sync(0xFFFFFFFFu, delta, o);
        np    += __shfl_down_sync(0xFFFFFFFFu, np,    o);
    }
    __shared__ float rs[8];
    __shared__ int   ri[8];
    if ((tid & 31) == 0) { rs[tid >> 5] = delta; ri[tid >> 5] = np; }
    __syncthreads();
    if (tid == 0) {
        float bs = 0.0f; int bn = 0;
        #pragma unroll
        for (int i = 0; i < 8; ++i) { bs += rs[i]; bn += ri[i]; }
        atomicAdd(&g_cls_sum, (double)bs);
        atomicAdd(&g_npos, bn);
    }

    __shared__ int is_last;
    __threadfence();
    if (tid == 0) is_last = (atomicAdd(&g_ticket, 1u) == EPI_GRID - 1);
    __syncthreads();
    if (!is_last) return;

    for (int i = tid; i < CELLS; i += EPI_BLK) g_acnt[i] = 0;  // restore

    float loss = 0.0f;
    int   nm = 0;
    for (int t = tid; t < NUM_T; t += EPI_BLK) {
        ull k = g_tkey[t];
        g_tkey[t] = 0ULL;                          // restore for next replay
        float tiou = __uint_as_float((unsigned)(k >> 32));
        if (tiou >= 0.5f) {
            nm++;
            int tor = g_tid_s[t];                  // sorted -> original
            unsigned aidx = 0xFFFFFFFFu - (unsigned)(k & 0xFFFFFFFFull);
            float4 abx = ((const float4*)anchors)[aidx];
            float4 tb  = ((const float4*)tboxes)[tor];
            float4 pr  = ((const float4*)boxes_preds)[aidx];
            float bw = tb.z - tb.x, bh = tb.w - tb.y;
            float bcx = tb.x + 0.5f * bw, bcy = tb.y + 0.5f * bh;
            float aww = abx.z - abx.x, ahh = abx.w - abx.y;
            float acx = abx.x + 0.5f * aww, acy = abx.y + 0.5f * ahh;
            float tx = (bcx - acx) / aww;
            float ty = (bcy - acy) / ahh;
            float tw = logf(fmaxf(bw, 1e-8f) / aww);
            float th = logf(fmaxf(bh, 1e-8f) / ahh);
            loss += sl1(pr.x - tx) + sl1(pr.y - ty)
                  + sl1(pr.z - tw) + sl1(pr.w - th);
        }
    }
    #pragma unroll
    for (int o = 16; o > 0; o >>= 1) {
        loss += __shfl_down_sync(0xFFFFFFFFu, loss, o);
        nm   += __shfl_down_sync(0xFFFFFFFFu, nm,   o);
    }
    __shared__ float frs[8];
    __shared__ int   frm[8];
    if ((tid & 31) == 0) { frs[tid >> 5] = loss; frm[tid >> 5] = nm; }
    __syncthreads();
    if (tid == 0) {
        float total = 0.0f; int tm = 0;
        #pragma unroll
        for (int i = 0; i < 8; ++i) { total += frs[i]; tm += frm[i]; }
        double cls_total = atomicAdd(&g_cls_sum, 0.0);
        int    npos      = atomicAdd(&g_npos, 0);
        double n_match   = (tm > 0) ? (double)tm : 1.0;
        double cls = cls_total / (double)npos;
        double reg = (double)total / (n_match * 4.0);
        out[0] = (float)(cls + reg);
        out[1] = (float)cls;
        out[2] = (float)reg;
        g_cls_sum = 0.0;
        g_npos    = 0;
        g_ticket  = 0u;
    }
}

// ---------------- launch -----------------------------------------------------
extern "C" void kernel_launch(void* const* d_in, const int* in_sizes, int n_in,
                              void* d_out, int out_size) {
    const float* cls_preds = (const float*)d_in[0];
    const float* box_preds = (const float*)d_in[1];
    const float* anchors   = (const float*)d_in[2];
    const float* tboxes    = (const float*)d_in[3];
    const int*   tlabels   = (const int*)d_in[4];
    float* out = (float*)d_out;

    acount_kernel<<<PREPG, PREPB>>>(anchors);
    scatter_kernel<<<PREPG + 1, PREPB>>>(anchors, tboxes);
    fused_kernel<<<MATCHB, BLK>>>(cls_preds);
    epilogue_kernel<<<EPI_GRID, EPI_BLK>>>(cls_preds, tlabels, box_preds,
                                           anchors, tboxes, out);
}